// round 11
// baseline (speedup 1.0000x reference)
#include <cuda_runtime.h>
#include <cuda_fp16.h>
#include <cstdint>

// ---------------------------------------------------------------------------
// y[b,i,t,e] = sum_{j,d} x[b,j,t,d] * sign[i,j]*W[widx[i,j]][d,e]*beta[e]
// == per-b GEMM: Y[4096 x 1024] = X[4096 x 1024(k=j,d)] @ WfT^T,
//    WfT[n=(i,e)][k=(j,d)] row-major (B operand).
//
// fp16 m16n8k16 legacy mma.sync at its issue-rate floor (~12.4 cyc/SMSP).
// x fp32->fp16 conversion fused into A staging with NO shuffles:
// each thread loads 8 consecutive floats (2x LDG.128), converts with
// 4x cvt.rn.f16x2, writes one swizzled STS.128. Spread across k-steps.
// ---------------------------------------------------------------------------

constexpr int NS = 3;                         // pipeline stages
constexpr int TILE_BYTES = 128 * 128;         // 128 rows x 64 fp16 (SW128 rows)
constexpr int STAGE_BYTES = 2 * TILE_BYTES;   // A + B
constexpr int SMEM_BYTES = NS * STAGE_BYTES;  // 98304 -> 2 CTAs/SM
constexpr int B_OFF = TILE_BYTES;

// Fused weight, transposed, fp16: WfT[n=(i,e)][k=(j,d)], beta+sign folded in.
__device__ __half g_WfT[1024 * 1024];

__constant__ float c_sign[64] = {
 +1,-1,-1,-1,-1,-1,-1,-1,
 +1,+1,+1,-1,+1,-1,-1,+1,
 +1,-1,+1,+1,+1,+1,-1,-1,
 +1,+1,-1,+1,+1,-1,+1,-1,
 +1,-1,-1,-1,+1,+1,+1,+1,
 +1,+1,-1,+1,-1,+1,-1,+1,
 +1,+1,+1,-1,-1,+1,+1,-1,
 +1,-1,+1,+1,-1,-1,+1,+1};
__constant__ int c_widx[64] = {
 0,1,2,3,4,5,6,7,
 1,0,3,2,5,4,7,6,
 2,3,0,1,6,7,4,5,
 3,2,1,0,7,6,5,4,
 4,5,6,7,0,1,2,3,
 5,4,7,6,1,0,3,2,
 6,7,4,5,2,3,0,1,
 7,6,5,4,3,2,1,0};

// ---------------- PTX helpers ----------------
__device__ __forceinline__ void cp_async16(uint32_t dst, const void* src) {
    asm volatile("cp.async.cg.shared.global [%0], [%1], 16;\n"
                 :: "r"(dst), "l"(src) : "memory");
}
__device__ __forceinline__ void cp_commit() {
    asm volatile("cp.async.commit_group;\n" ::: "memory");
}
template <int N>
__device__ __forceinline__ void cp_wait() {
    asm volatile("cp.async.wait_group %0;\n" :: "n"(N) : "memory");
}
__device__ __forceinline__ uint32_t smem_u32(const void* p) {
    uint32_t a;
    asm("{ .reg .u64 t; cvta.to.shared.u64 t, %1; cvt.u32.u64 %0, t; }"
        : "=r"(a) : "l"(p));
    return a;
}
__device__ __forceinline__ void ldsm_x4(uint32_t* r, uint32_t addr) {
    asm volatile("ldmatrix.sync.aligned.m8n8.x4.shared.b16 {%0,%1,%2,%3}, [%4];"
                 : "=r"(r[0]), "=r"(r[1]), "=r"(r[2]), "=r"(r[3]) : "r"(addr));
}
__device__ __forceinline__ void sts128(uint32_t addr, uint32_t v0, uint32_t v1,
                                       uint32_t v2, uint32_t v3) {
    asm volatile("st.shared.v4.b32 [%0], {%1,%2,%3,%4};"
                 :: "r"(addr), "r"(v0), "r"(v1), "r"(v2), "r"(v3) : "memory");
}
// pack2(a,b): fp16(a) in low 16 bits, fp16(b) in high 16 bits (RN).
__device__ __forceinline__ uint32_t pack2(float a, float b) {
    uint32_t r;
    asm("cvt.rn.f16x2.f32 %0, %1, %2;" : "=r"(r) : "f"(b), "f"(a));
    return r;
}

// ---------------- Wf prep (transposed, fp16) ----------------
__global__ void prep_wf_kernel(const float* __restrict__ W,
                               const float* __restrict__ beta) {
    __shared__ float s[32][33];
    const int kb = blockIdx.x * 32;
    const int nb = blockIdx.y * 32;
    const int i = nb >> 7, j = kb >> 7;
    const float sg = c_sign[i * 8 + j];
    const int w = c_widx[i * 8 + j];
    const int e0 = nb & 127, d0 = kb & 127;
    s[threadIdx.y][threadIdx.x] =
        W[(w << 14) + (d0 + threadIdx.y) * 128 + (e0 + threadIdx.x)];
    __syncthreads();
    const float v = s[threadIdx.x][threadIdx.y] * sg * beta[e0 + threadIdx.y];
    g_WfT[(size_t)(nb + threadIdx.y) * 1024 + kb + threadIdx.x] =
        __float2half_rn(v);
}

// ---------------- main GEMM ----------------
__global__ __launch_bounds__(256, 2)
void octo_gemm_kernel(const float* __restrict__ x, float* __restrict__ y) {
    extern __shared__ __align__(128) char smc[];
    const uint32_t sbase = smem_u32(smc);
    const int tid = threadIdx.x;
    const int lane = tid & 31;
    const int warp = tid >> 5;
    const int warp_m = warp & 1;   // 2 warps over M
    const int warp_n = warp >> 1;  // 4 warps over N

    const int nb = blockIdx.x;         // head i
    const int t0 = blockIdx.y * 128;   // t tile
    const int b  = blockIdx.z;

    const __half* gB = g_WfT + ((size_t)nb * 128) * 1024;
    const float*  xb = x + (size_t)b * (8u * 4096u * 128u);

    // ---- B staging (cp.async, SW128) ----
    auto issueB = [&](int kc) {
        const uint32_t b_base = sbase + (uint32_t)((kc % NS) * STAGE_BYTES) + B_OFF;
        const __half* srcB = gB + kc * 64;
        #pragma unroll
        for (int it = 0; it < 4; it++) {
            const int id = tid + 256 * it;
            const int r = id >> 3, ch = id & 7;
            const uint32_t off = (uint32_t)(r * 128 + ((ch * 16) ^ ((r & 7) * 16)));
            cp_async16(b_base + off, srcB + (size_t)r * 1024 + ch * 8);
        }
    };

    // ---- fused A conversion, shuffle-free ----
    // Each thread owns one 16B output chunk: 8 consecutive floats -> 4 f16x2.
    // Pass p covers rows 32p..32p+31 of the 128-row tile.
    const int cvr = tid >> 3;          // row within pass (0..31)
    const int cch = tid & 7;           // 16B chunk within row
    float4 F0, F1;
    auto convLoad = [&](int kcc, int p) {
        const int r = cvr + 32 * p;
        const float* src = xb + ((size_t)(kcc >> 1) * 4096 + t0 + r) * 128
                              + (kcc & 1) * 64 + cch * 8;
        F0 = *reinterpret_cast<const float4*>(src);
        F1 = *reinterpret_cast<const float4*>(src + 4);
    };
    auto convStore = [&](int kcc, int p) {
        const int r = cvr + 32 * p;
        const uint32_t a_base = sbase + (uint32_t)((kcc % NS) * STAGE_BYTES);
        const uint32_t off = (uint32_t)(r * 128 + ((cch * 16) ^ ((r & 7) * 16)));
        sts128(a_base + off,
               pack2(F0.x, F0.y), pack2(F0.z, F0.w),
               pack2(F1.x, F1.y), pack2(F1.z, F1.w));
    };

    // ---- fragment addressing (SW128) ----
    const int aRow = warp_m * 64 + ((lane >> 3) & 1) * 8 + (lane & 7);
    const uint32_t aAdj = (uint32_t)(((lane >> 4) & 1) << 4);
    const uint32_t aXor = (uint32_t)((aRow & 7) << 4);
    const int bRow = warp_n * 32 + ((lane >> 4) & 1) * 8 + (lane & 7);
    const uint32_t bAdj = (uint32_t)(((lane >> 3) & 1) << 4);
    const uint32_t bXor = (uint32_t)((bRow & 7) << 4);

    uint32_t aF[2][4][4];
    uint32_t bF[2][4];

    auto ldA = [&](int buf, uint32_t stg, int ks) {
        const uint32_t co = (uint32_t)((ks << 5) | aAdj) ^ aXor;
        const uint32_t base = stg + (uint32_t)(aRow * 128) + co;
        #pragma unroll
        for (int mt = 0; mt < 4; mt++) ldsm_x4(aF[buf][mt], base + mt * 2048);
    };
    auto ldB = [&](uint32_t stg, int ks) {
        const uint32_t co = (uint32_t)((ks << 5) | bAdj) ^ bXor;
        const uint32_t base = stg + (uint32_t)B_OFF + (uint32_t)(bRow * 128) + co;
        #pragma unroll
        for (int pr = 0; pr < 2; pr++) ldsm_x4(bF[pr], base + pr * 2048);
    };

    float acc[4][4][4];
    #pragma unroll
    for (int mt = 0; mt < 4; mt++)
        #pragma unroll
        for (int nt = 0; nt < 4; nt++)
            #pragma unroll
            for (int c = 0; c < 4; c++) acc[mt][nt][c] = 0.0f;

    auto do_mmas = [&](int buf) {
        #pragma unroll
        for (int mt = 0; mt < 4; mt++)
            #pragma unroll
            for (int nt = 0; nt < 4; nt++) {
                const uint32_t* bp = &bF[nt >> 1][(nt & 1) * 2];
                asm volatile(
                    "mma.sync.aligned.m16n8k16.row.col.f32.f16.f16.f32 "
                    "{%0,%1,%2,%3}, {%4,%5,%6,%7}, {%8,%9}, {%0,%1,%2,%3};\n"
                    : "+f"(acc[mt][nt][0]), "+f"(acc[mt][nt][1]),
                      "+f"(acc[mt][nt][2]), "+f"(acc[mt][nt][3])
                    : "r"(aF[buf][mt][0]), "r"(aF[buf][mt][1]),
                      "r"(aF[buf][mt][2]), "r"(aF[buf][mt][3]),
                      "r"(bp[0]), "r"(bp[1]));
            }
    };

    // ---- prologue: stages 0,1 ----
    #pragma unroll
    for (int p = 0; p < 4; p++) { convLoad(0, p); convStore(0, p); }
    #pragma unroll
    for (int p = 0; p < 4; p++) { convLoad(1, p); convStore(1, p); }
    issueB(0); cp_commit();
    issueB(1); cp_commit();
    cp_wait<NS - 2>();
    __syncthreads();
    ldA(0, sbase, 0);

    for (int kc = 0; kc < 16; kc++) {
        const uint32_t stg = sbase + (uint32_t)((kc % NS) * STAGE_BYTES);
        const bool doConv = (kc + 2 < 16);
        if (doConv) issueB(kc + 2);
        cp_commit();                      // empty tail groups keep counts uniform

        #pragma unroll
        for (int ks = 0; ks < 4; ks++) {
            ldB(stg, ks);                              // single-buffer B frags
            if (ks < 3) {
                ldA((ks + 1) & 1, stg, ks + 1);        // A frags for next ks
            } else if (kc < 15) {
                // barrier + next-stage ks0 frags hidden behind ks3 MMAs below
                cp_wait<NS - 2>();
                __syncthreads();
                ldA(0, sbase + (uint32_t)(((kc + 1) % NS) * STAGE_BYTES), 0);
            }
            if (doConv) convLoad(kc + 2, ks);          // LDG hides under MMAs
            do_mmas(ks & 1);
            if (doConv) convStore(kc + 2, ks);
        }
    }

    // ---- epilogue: y[b][i=nb][t][e] ----
    float* yb = y + ((size_t)b * 8 + nb) * 4096u * 128u;
    #pragma unroll
    for (int mt = 0; mt < 4; mt++) {
        const int row = t0 + warp_m * 64 + mt * 16 + (lane >> 2);
        #pragma unroll
        for (int nt = 0; nt < 4; nt++) {
            const int e = warp_n * 32 + nt * 8 + (lane & 3) * 2;
            *reinterpret_cast<float2*>(yb + (size_t)row * 128 + e) =
                make_float2(acc[mt][nt][0], acc[mt][nt][1]);
            *reinterpret_cast<float2*>(yb + (size_t)(row + 8) * 128 + e) =
                make_float2(acc[mt][nt][2], acc[mt][nt][3]);
        }
    }
}

extern "C" void kernel_launch(void* const* d_in, const int* in_sizes, int n_in,
                              void* d_out, int out_size) {
    const float* x    = (const float*)d_in[0];   // [8,8,4096,128] fp32
    const float* W    = (const float*)d_in[1];   // [8,128,128] fp32
    const float* beta = (const float*)d_in[2];   // [128] fp32
    float* y = (float*)d_out;                    // [8,8,4096,128] fp32
    (void)in_sizes; (void)n_in; (void)out_size;

    cudaFuncSetAttribute(octo_gemm_kernel,
                         cudaFuncAttributeMaxDynamicSharedMemorySize, SMEM_BYTES);

    prep_wf_kernel<<<dim3(32, 32), dim3(32, 32)>>>(W, beta);

    dim3 grid(8, 32, 8);   // n-tiles fastest: 8 CTAs share each x tile in L2
    octo_gemm_kernel<<<grid, 256, SMEM_BYTES>>>(x, y);
}

// round 12
// speedup vs baseline: 1.0129x; 1.0129x over previous
#include <cuda_runtime.h>
#include <cuda_fp16.h>
#include <cstdint>

// ---------------------------------------------------------------------------
// y[b,i,t,e] = sum_{j,d} x[b,j,t,d] * sign[i,j]*W[widx[i,j]][d,e]*beta[e]
// == per-b GEMM: Y[4096 x 1024] = X[4096 x 1024(k=j,d)] @ WfT^T,
//    WfT[n=(i,e)][k=(j,d)] row-major (B operand).
//
// fp16 m16n8k16 legacy mma.sync at its issue-rate floor (~12.4 cyc/SMSP).
// x fp32->fp16 conversion fused into A staging with NO shuffles:
// each thread loads 8 consecutive floats (2x LDG.128), converts with
// 4x cvt.rn.f16x2, writes one swizzled STS.128. Spread across k-steps.
// ---------------------------------------------------------------------------

constexpr int NS = 3;                         // pipeline stages
constexpr int TILE_BYTES = 128 * 128;         // 128 rows x 64 fp16 (SW128 rows)
constexpr int STAGE_BYTES = 2 * TILE_BYTES;   // A + B
constexpr int SMEM_BYTES = NS * STAGE_BYTES;  // 98304 -> 2 CTAs/SM
constexpr int B_OFF = TILE_BYTES;

// Fused weight, transposed, fp16: WfT[n=(i,e)][k=(j,d)], beta+sign folded in.
__device__ __half g_WfT[1024 * 1024];

__constant__ float c_sign[64] = {
 +1,-1,-1,-1,-1,-1,-1,-1,
 +1,+1,+1,-1,+1,-1,-1,+1,
 +1,-1,+1,+1,+1,+1,-1,-1,
 +1,+1,-1,+1,+1,-1,+1,-1,
 +1,-1,-1,-1,+1,+1,+1,+1,
 +1,+1,-1,+1,-1,+1,-1,+1,
 +1,+1,+1,-1,-1,+1,+1,-1,
 +1,-1,+1,+1,-1,-1,+1,+1};
__constant__ int c_widx[64] = {
 0,1,2,3,4,5,6,7,
 1,0,3,2,5,4,7,6,
 2,3,0,1,6,7,4,5,
 3,2,1,0,7,6,5,4,
 4,5,6,7,0,1,2,3,
 5,4,7,6,1,0,3,2,
 6,7,4,5,2,3,0,1,
 7,6,5,4,3,2,1,0};

// ---------------- PTX helpers ----------------
__device__ __forceinline__ void cp_async16(uint32_t dst, const void* src) {
    asm volatile("cp.async.cg.shared.global [%0], [%1], 16;\n"
                 :: "r"(dst), "l"(src) : "memory");
}
__device__ __forceinline__ void cp_commit() {
    asm volatile("cp.async.commit_group;\n" ::: "memory");
}
template <int N>
__device__ __forceinline__ void cp_wait() {
    asm volatile("cp.async.wait_group %0;\n" :: "n"(N) : "memory");
}
__device__ __forceinline__ uint32_t smem_u32(const void* p) {
    uint32_t a;
    asm("{ .reg .u64 t; cvta.to.shared.u64 t, %1; cvt.u32.u64 %0, t; }"
        : "=r"(a) : "l"(p));
    return a;
}
__device__ __forceinline__ void ldsm_x4(uint32_t* r, uint32_t addr) {
    asm volatile("ldmatrix.sync.aligned.m8n8.x4.shared.b16 {%0,%1,%2,%3}, [%4];"
                 : "=r"(r[0]), "=r"(r[1]), "=r"(r[2]), "=r"(r[3]) : "r"(addr));
}
__device__ __forceinline__ void sts128(uint32_t addr, uint32_t v0, uint32_t v1,
                                       uint32_t v2, uint32_t v3) {
    asm volatile("st.shared.v4.b32 [%0], {%1,%2,%3,%4};"
                 :: "r"(addr), "r"(v0), "r"(v1), "r"(v2), "r"(v3) : "memory");
}
// pack2(a,b): fp16(a) in low 16 bits, fp16(b) in high 16 bits (RN).
__device__ __forceinline__ uint32_t pack2(float a, float b) {
    uint32_t r;
    asm("cvt.rn.f16x2.f32 %0, %1, %2;" : "=r"(r) : "f"(b), "f"(a));
    return r;
}

// ---------------- Wf prep (transposed, fp16) ----------------
__global__ void prep_wf_kernel(const float* __restrict__ W,
                               const float* __restrict__ beta) {
    __shared__ float s[32][33];
    const int kb = blockIdx.x * 32;
    const int nb = blockIdx.y * 32;
    const int i = nb >> 7, j = kb >> 7;
    const float sg = c_sign[i * 8 + j];
    const int w = c_widx[i * 8 + j];
    const int e0 = nb & 127, d0 = kb & 127;
    s[threadIdx.y][threadIdx.x] =
        W[(w << 14) + (d0 + threadIdx.y) * 128 + (e0 + threadIdx.x)];
    __syncthreads();
    const float v = s[threadIdx.x][threadIdx.y] * sg * beta[e0 + threadIdx.y];
    g_WfT[(size_t)(nb + threadIdx.y) * 1024 + kb + threadIdx.x] =
        __float2half_rn(v);
}

// ---------------- main GEMM ----------------
__global__ __launch_bounds__(256, 2)
void octo_gemm_kernel(const float* __restrict__ x, float* __restrict__ y) {
    extern __shared__ __align__(128) char smc[];
    const uint32_t sbase = smem_u32(smc);
    const int tid = threadIdx.x;
    const int lane = tid & 31;
    const int warp = tid >> 5;
    const int warp_m = warp & 1;   // 2 warps over M
    const int warp_n = warp >> 1;  // 4 warps over N

    const int nb = blockIdx.x;         // head i
    const int t0 = blockIdx.y * 128;   // t tile
    const int b  = blockIdx.z;

    const __half* gB = g_WfT + ((size_t)nb * 128) * 1024;
    const float*  xb = x + (size_t)b * (8u * 4096u * 128u);

    // ---- B staging (cp.async, SW128) ----
    auto issueB = [&](int kc) {
        const uint32_t b_base = sbase + (uint32_t)((kc % NS) * STAGE_BYTES) + B_OFF;
        const __half* srcB = gB + kc * 64;
        #pragma unroll
        for (int it = 0; it < 4; it++) {
            const int id = tid + 256 * it;
            const int r = id >> 3, ch = id & 7;
            const uint32_t off = (uint32_t)(r * 128 + ((ch * 16) ^ ((r & 7) * 16)));
            cp_async16(b_base + off, srcB + (size_t)r * 1024 + ch * 8);
        }
    };

    // ---- fused A conversion, shuffle-free ----
    // Each thread owns one 16B output chunk: 8 consecutive floats -> 4 f16x2.
    // Pass p covers rows 32p..32p+31 of the 128-row tile.
    const int cvr = tid >> 3;          // row within pass (0..31)
    const int cch = tid & 7;           // 16B chunk within row
    float4 F0, F1;
    auto convLoad = [&](int kcc, int p) {
        const int r = cvr + 32 * p;
        const float* src = xb + ((size_t)(kcc >> 1) * 4096 + t0 + r) * 128
                              + (kcc & 1) * 64 + cch * 8;
        F0 = *reinterpret_cast<const float4*>(src);
        F1 = *reinterpret_cast<const float4*>(src + 4);
    };
    auto convStore = [&](int kcc, int p) {
        const int r = cvr + 32 * p;
        const uint32_t a_base = sbase + (uint32_t)((kcc % NS) * STAGE_BYTES);
        const uint32_t off = (uint32_t)(r * 128 + ((cch * 16) ^ ((r & 7) * 16)));
        sts128(a_base + off,
               pack2(F0.x, F0.y), pack2(F0.z, F0.w),
               pack2(F1.x, F1.y), pack2(F1.z, F1.w));
    };

    // ---- fragment addressing (SW128) ----
    const int aRow = warp_m * 64 + ((lane >> 3) & 1) * 8 + (lane & 7);
    const uint32_t aAdj = (uint32_t)(((lane >> 4) & 1) << 4);
    const uint32_t aXor = (uint32_t)((aRow & 7) << 4);
    const int bRow = warp_n * 32 + ((lane >> 4) & 1) * 8 + (lane & 7);
    const uint32_t bAdj = (uint32_t)(((lane >> 3) & 1) << 4);
    const uint32_t bXor = (uint32_t)((bRow & 7) << 4);

    uint32_t aF[2][4][4];
    uint32_t bF[2][4];

    auto ldA = [&](int buf, uint32_t stg, int ks) {
        const uint32_t co = (uint32_t)((ks << 5) | aAdj) ^ aXor;
        const uint32_t base = stg + (uint32_t)(aRow * 128) + co;
        #pragma unroll
        for (int mt = 0; mt < 4; mt++) ldsm_x4(aF[buf][mt], base + mt * 2048);
    };
    auto ldB = [&](uint32_t stg, int ks) {
        const uint32_t co = (uint32_t)((ks << 5) | bAdj) ^ bXor;
        const uint32_t base = stg + (uint32_t)B_OFF + (uint32_t)(bRow * 128) + co;
        #pragma unroll
        for (int pr = 0; pr < 2; pr++) ldsm_x4(bF[pr], base + pr * 2048);
    };

    float acc[4][4][4];
    #pragma unroll
    for (int mt = 0; mt < 4; mt++)
        #pragma unroll
        for (int nt = 0; nt < 4; nt++)
            #pragma unroll
            for (int c = 0; c < 4; c++) acc[mt][nt][c] = 0.0f;

    auto do_mmas = [&](int buf) {
        #pragma unroll
        for (int mt = 0; mt < 4; mt++)
            #pragma unroll
            for (int nt = 0; nt < 4; nt++) {
                const uint32_t* bp = &bF[nt >> 1][(nt & 1) * 2];
                asm volatile(
                    "mma.sync.aligned.m16n8k16.row.col.f32.f16.f16.f32 "
                    "{%0,%1,%2,%3}, {%4,%5,%6,%7}, {%8,%9}, {%0,%1,%2,%3};\n"
                    : "+f"(acc[mt][nt][0]), "+f"(acc[mt][nt][1]),
                      "+f"(acc[mt][nt][2]), "+f"(acc[mt][nt][3])
                    : "r"(aF[buf][mt][0]), "r"(aF[buf][mt][1]),
                      "r"(aF[buf][mt][2]), "r"(aF[buf][mt][3]),
                      "r"(bp[0]), "r"(bp[1]));
            }
    };

    // ---- prologue: stages 0,1 ----
    #pragma unroll
    for (int p = 0; p < 4; p++) { convLoad(0, p); convStore(0, p); }
    #pragma unroll
    for (int p = 0; p < 4; p++) { convLoad(1, p); convStore(1, p); }
    issueB(0); cp_commit();
    issueB(1); cp_commit();
    cp_wait<NS - 2>();
    __syncthreads();
    ldA(0, sbase, 0);

    for (int kc = 0; kc < 16; kc++) {
        const uint32_t stg = sbase + (uint32_t)((kc % NS) * STAGE_BYTES);
        const bool doConv = (kc + 2 < 16);
        if (doConv) issueB(kc + 2);
        cp_commit();                      // empty tail groups keep counts uniform

        #pragma unroll
        for (int ks = 0; ks < 4; ks++) {
            ldB(stg, ks);                              // single-buffer B frags
            if (ks < 3) {
                ldA((ks + 1) & 1, stg, ks + 1);        // A frags for next ks
            } else if (kc < 15) {
                // barrier + next-stage ks0 frags hidden behind ks3 MMAs below
                cp_wait<NS - 2>();
                __syncthreads();
                ldA(0, sbase + (uint32_t)(((kc + 1) % NS) * STAGE_BYTES), 0);
            }
            if (doConv) convLoad(kc + 2, ks);          // LDG hides under MMAs
            do_mmas(ks & 1);
            if (doConv) convStore(kc + 2, ks);
        }
    }

    // ---- epilogue: y[b][i=nb][t][e] ----
    float* yb = y + ((size_t)b * 8 + nb) * 4096u * 128u;
    #pragma unroll
    for (int mt = 0; mt < 4; mt++) {
        const int row = t0 + warp_m * 64 + mt * 16 + (lane >> 2);
        #pragma unroll
        for (int nt = 0; nt < 4; nt++) {
            const int e = warp_n * 32 + nt * 8 + (lane & 3) * 2;
            *reinterpret_cast<float2*>(yb + (size_t)row * 128 + e) =
                make_float2(acc[mt][nt][0], acc[mt][nt][1]);
            *reinterpret_cast<float2*>(yb + (size_t)(row + 8) * 128 + e) =
                make_float2(acc[mt][nt][2], acc[mt][nt][3]);
        }
    }
}

extern "C" void kernel_launch(void* const* d_in, const int* in_sizes, int n_in,
                              void* d_out, int out_size) {
    const float* x    = (const float*)d_in[0];   // [8,8,4096,128] fp32
    const float* W    = (const float*)d_in[1];   // [8,128,128] fp32
    const float* beta = (const float*)d_in[2];   // [128] fp32
    float* y = (float*)d_out;                    // [8,8,4096,128] fp32
    (void)in_sizes; (void)n_in; (void)out_size;

    cudaFuncSetAttribute(octo_gemm_kernel,
                         cudaFuncAttributeMaxDynamicSharedMemorySize, SMEM_BYTES);

    prep_wf_kernel<<<dim3(32, 32), dim3(32, 32)>>>(W, beta);

    dim3 grid(8, 32, 8);   // n-tiles fastest: 8 CTAs share each x tile in L2
    octo_gemm_kernel<<<grid, 256, SMEM_BYTES>>>(x, y);
}

// round 13
// speedup vs baseline: 1.3443x; 1.3273x over previous
#include <cuda_runtime.h>
#include <cuda_fp16.h>
#include <cstdint>

// ---------------------------------------------------------------------------
// y[b,i,t,e] = sum_{j,d} x[b,j,t,d] * sign[i,j]*W[widx[i,j]][d,e]*beta[e]
// == per-b GEMM: Y[4096 x 1024] = X[4096 x 1024(k=j,d)] @ WfT^T,
//    WfT[n=(i,e)][k=(j,d)] row-major (B operand).
//
// fp16 m16n8k16 legacy mma.sync at its issue-rate floor (~12.4 cyc/SMSP).
// Split conversion (fused variant measured +100us twice -> reverted):
// conv_x does fp32->fp16 at 32B/thread; GEMM identical to the 230us R8 best.
// ---------------------------------------------------------------------------

constexpr int NS = 3;                    // pipeline stages
constexpr int LDH = 72;                  // smem row stride in fp16 (64 + 8 pad)
constexpr int TILE_H_BYTES = 128 * LDH * 2;          // 18432 per operand tile
constexpr int STAGE_BYTES = 2 * TILE_H_BYTES;        // 36864
constexpr int SMEM_BYTES = NS * STAGE_BYTES;         // 110592 -> 2 CTAs/SM
constexpr int B_OFF_BYTES = TILE_H_BYTES;

// x converted to fp16, same [b][j][t][d] layout (67 MB scratch).
__device__ __half g_xh[8u * 8u * 4096u * 128u];
// Fused weight, transposed, fp16: WfT[n=(i,e)][k=(j,d)], beta+sign folded in.
__device__ __half g_WfT[1024 * 1024];

__constant__ float c_sign[64] = {
 +1,-1,-1,-1,-1,-1,-1,-1,
 +1,+1,+1,-1,+1,-1,-1,+1,
 +1,-1,+1,+1,+1,+1,-1,-1,
 +1,+1,-1,+1,+1,-1,+1,-1,
 +1,-1,-1,-1,+1,+1,+1,+1,
 +1,+1,-1,+1,-1,+1,-1,+1,
 +1,+1,+1,-1,-1,+1,+1,-1,
 +1,-1,+1,+1,-1,-1,+1,+1};
__constant__ int c_widx[64] = {
 0,1,2,3,4,5,6,7,
 1,0,3,2,5,4,7,6,
 2,3,0,1,6,7,4,5,
 3,2,1,0,7,6,5,4,
 4,5,6,7,0,1,2,3,
 5,4,7,6,1,0,3,2,
 6,7,4,5,2,3,0,1,
 7,6,5,4,3,2,1,0};

// ---------------- PTX helpers ----------------
__device__ __forceinline__ void cp_async16(uint32_t dst, const void* src) {
    asm volatile("cp.async.cg.shared.global [%0], [%1], 16;\n"
                 :: "r"(dst), "l"(src) : "memory");
}
__device__ __forceinline__ void cp_commit() {
    asm volatile("cp.async.commit_group;\n" ::: "memory");
}
template <int N>
__device__ __forceinline__ void cp_wait() {
    asm volatile("cp.async.wait_group %0;\n" :: "n"(N) : "memory");
}
__device__ __forceinline__ uint32_t smem_u32(const void* p) {
    uint32_t a;
    asm("{ .reg .u64 t; cvta.to.shared.u64 t, %1; cvt.u32.u64 %0, t; }"
        : "=r"(a) : "l"(p));
    return a;
}
__device__ __forceinline__ void ldsm_x4(uint32_t* r, uint32_t addr) {
    asm volatile("ldmatrix.sync.aligned.m8n8.x4.shared.b16 {%0,%1,%2,%3}, [%4];"
                 : "=r"(r[0]), "=r"(r[1]), "=r"(r[2]), "=r"(r[3]) : "r"(addr));
}
// pack2(a,b): fp16(a) in low 16 bits, fp16(b) in high 16 bits (RN).
__device__ __forceinline__ uint32_t pack2(float a, float b) {
    uint32_t r;
    asm("cvt.rn.f16x2.f32 %0, %1, %2;" : "=r"(r) : "f"(b), "f"(a));
    return r;
}

// ---------------- x fp32 -> fp16 conversion (32B out per thread) ----------------
__global__ void conv_x_kernel(const float* __restrict__ x) {
    const size_t i = (size_t)blockIdx.x * 256 + threadIdx.x;   // 4.19M threads
    const float4* xv = reinterpret_cast<const float4*>(x);
    const float4 a = xv[2 * i];
    const float4 b = xv[2 * i + 1];
    uint4 o;
    o.x = pack2(a.x, a.y);
    o.y = pack2(a.z, a.w);
    o.z = pack2(b.x, b.y);
    o.w = pack2(b.z, b.w);
    reinterpret_cast<uint4*>(g_xh)[i] = o;
}

// ---------------- Wf prep (transposed, fp16) ----------------
__global__ void prep_wf_kernel(const float* __restrict__ W,
                               const float* __restrict__ beta) {
    __shared__ float s[32][33];
    const int kb = blockIdx.x * 32;   // k tile
    const int nb = blockIdx.y * 32;   // n tile
    const int i = nb >> 7, j = kb >> 7;
    const float sg = c_sign[i * 8 + j];
    const int w = c_widx[i * 8 + j];
    const int e0 = nb & 127, d0 = kb & 127;
    s[threadIdx.y][threadIdx.x] =
        W[(w << 14) + (d0 + threadIdx.y) * 128 + (e0 + threadIdx.x)];
    __syncthreads();
    const float v = s[threadIdx.x][threadIdx.y] * sg * beta[e0 + threadIdx.y];
    g_WfT[(size_t)(nb + threadIdx.y) * 1024 + kb + threadIdx.x] =
        __float2half_rn(v);
}

// ---------------- main GEMM (fp16 m16n8k16, cross-kc pipelined) ----------------
__global__ __launch_bounds__(256, 2)
void octo_gemm_kernel(float* __restrict__ y) {
    extern __shared__ __align__(128) char smc[];
    const uint32_t sbase = smem_u32(smc);
    const int tid = threadIdx.x;
    const int lane = tid & 31;
    const int warp = tid >> 5;
    const int warp_m = warp & 1;   // 2 warps over M (64 rows each)
    const int warp_n = warp >> 1;  // 4 warps over N (32 cols each)

    const int nb = blockIdx.x;         // 0..7 -> head i
    const int t0 = blockIdx.y * 128;   // t tile
    const int b  = blockIdx.z;

    // cp.async mapping: 128 rows x 8 chunks(16B = 8 fp16)
    const int cr = tid >> 3;
    const int cc = tid & 7;

    const __half* xb = g_xh + (size_t)b * (8u * 4096u * 128u);
    const __half* gB = g_WfT + ((size_t)nb * 128) * 1024;

    auto issue_stage = [&](int kc) {   // kc 0..15, K-chunk = 64 fp16
        const int s = kc % NS;
        const uint32_t a_base = sbase + (uint32_t)(s * STAGE_BYTES);
        const uint32_t b_base = a_base + B_OFF_BYTES;
        const int j = kc >> 1;
        const int d0 = (kc & 1) * 64;
        const __half* srcA = xb + ((size_t)j * 4096 + t0) * 128 + d0;
        const __half* srcB = gB + kc * 64;
        #pragma unroll
        for (int it = 0; it < 4; it++) {
            const int r = cr + 32 * it;
            cp_async16(a_base + (uint32_t)(r * LDH + cc * 8) * 2u,
                       srcA + (size_t)r * 128 + cc * 8);
            cp_async16(b_base + (uint32_t)(r * LDH + cc * 8) * 2u,
                       srcB + (size_t)r * 1024 + cc * 8);
        }
    };

    float acc[4][4][4];
    #pragma unroll
    for (int mt = 0; mt < 4; mt++)
        #pragma unroll
        for (int nt = 0; nt < 4; nt++)
            #pragma unroll
            for (int c = 0; c < 4; c++) acc[mt][nt][c] = 0.0f;

    // ldmatrix lane addressing (byte offsets within a stage)
    const uint32_t a_row = (uint32_t)(warp_m * 64 + ((lane >> 3) & 1) * 8 + (lane & 7));
    const uint32_t a_off0 = (a_row * LDH + ((lane >> 4) & 1) * 8) * 2u;
    const uint32_t b_row = (uint32_t)(warp_n * 32 + ((lane >> 4) & 1) * 8 + (lane & 7));
    const uint32_t b_off0 = (uint32_t)B_OFF_BYTES +
                            (b_row * LDH + ((lane >> 3) & 1) * 8) * 2u;

    uint32_t aF[2][4][4];   // [buf][mt][reg]
    uint32_t bF[2][2][4];   // [buf][pr][reg]: {b0,b1} of nt=2pr then 2pr+1

    auto prefetch = [&](int buf, uint32_t aS, uint32_t bS, int ks) {
        const uint32_t ao = aS + ks * 32;   // 16 fp16 = 32 B per k-step
        const uint32_t bo = bS + ks * 32;
        #pragma unroll
        for (int mt = 0; mt < 4; mt++)
            ldsm_x4(aF[buf][mt], ao + mt * (16 * LDH * 2));
        #pragma unroll
        for (int pr = 0; pr < 2; pr++)
            ldsm_x4(bF[buf][pr], bo + pr * (16 * LDH * 2));
    };
    auto do_mmas = [&](int buf) {
        #pragma unroll
        for (int mt = 0; mt < 4; mt++)
            #pragma unroll
            for (int nt = 0; nt < 4; nt++) {
                const uint32_t* bp = &bF[buf][nt >> 1][(nt & 1) * 2];
                asm volatile(
                    "mma.sync.aligned.m16n8k16.row.col.f32.f16.f16.f32 "
                    "{%0,%1,%2,%3}, {%4,%5,%6,%7}, {%8,%9}, {%0,%1,%2,%3};\n"
                    : "+f"(acc[mt][nt][0]), "+f"(acc[mt][nt][1]),
                      "+f"(acc[mt][nt][2]), "+f"(acc[mt][nt][3])
                    : "r"(aF[buf][mt][0]), "r"(aF[buf][mt][1]),
                      "r"(aF[buf][mt][2]), "r"(aF[buf][mt][3]),
                      "r"(bp[0]), "r"(bp[1]));
            }
    };

    // prologue: 2 stages in flight, stage 0 ready, ks0 fragments loaded
    issue_stage(0); cp_commit();
    issue_stage(1); cp_commit();
    cp_wait<NS - 2>();
    __syncthreads();
    prefetch(0, sbase + a_off0, sbase + b_off0, 0);

    for (int kc = 0; kc < 16; kc++) {
        const uint32_t stg = sbase + (uint32_t)((kc % NS) * STAGE_BYTES);
        const uint32_t aS = stg + a_off0;
        const uint32_t bS = stg + b_off0;

        if (kc + 2 < 16) issue_stage(kc + 2);
        cp_commit();                      // empty tail groups keep counts uniform

        #pragma unroll
        for (int ks = 0; ks < 3; ks++) {  // ks0..2: prefetch ks+1, then MMA ks
            prefetch((ks + 1) & 1, aS, bS, ks + 1);
            do_mmas(ks & 1);
        }

        if (kc < 15) {
            // barrier + next-stage ks0 ldmatrix hidden behind ks=3 MMAs below
            cp_wait<NS - 2>();
            __syncthreads();
            const uint32_t nstg = sbase + (uint32_t)(((kc + 1) % NS) * STAGE_BYTES);
            prefetch(0, nstg + a_off0, nstg + b_off0, 0);
        }
        do_mmas(1);                       // ks=3 (fragments loaded at ks==2)
    }

    // epilogue: y[b][i=nb][t][e]
    float* yb = y + ((size_t)b * 8 + nb) * 4096u * 128u;
    #pragma unroll
    for (int mt = 0; mt < 4; mt++) {
        const int row = t0 + warp_m * 64 + mt * 16 + (lane >> 2);
        #pragma unroll
        for (int nt = 0; nt < 4; nt++) {
            const int e = warp_n * 32 + nt * 8 + (lane & 3) * 2;
            *reinterpret_cast<float2*>(yb + (size_t)row * 128 + e) =
                make_float2(acc[mt][nt][0], acc[mt][nt][1]);
            *reinterpret_cast<float2*>(yb + (size_t)(row + 8) * 128 + e) =
                make_float2(acc[mt][nt][2], acc[mt][nt][3]);
        }
    }
}

extern "C" void kernel_launch(void* const* d_in, const int* in_sizes, int n_in,
                              void* d_out, int out_size) {
    const float* x    = (const float*)d_in[0];   // [8,8,4096,128] fp32
    const float* W    = (const float*)d_in[1];   // [8,128,128] fp32
    const float* beta = (const float*)d_in[2];   // [128] fp32
    float* y = (float*)d_out;                    // [8,8,4096,128] fp32
    (void)in_sizes; (void)n_in; (void)out_size;

    cudaFuncSetAttribute(octo_gemm_kernel,
                         cudaFuncAttributeMaxDynamicSharedMemorySize, SMEM_BYTES);

    conv_x_kernel<<<16384, 256>>>(x);                    // 33.5M elems / 8 per thread
    prep_wf_kernel<<<dim3(32, 32), dim3(32, 32)>>>(W, beta);

    dim3 grid(8, 32, 8);   // n-tiles fastest: 8 CTAs share each x tile in L2
    octo_gemm_kernel<<<grid, 256, SMEM_BYTES>>>(y);
}